// round 16
// baseline (speedup 1.0000x reference)
#include <cuda_runtime.h>
#include <cuda_fp16.h>
#include <math.h>
#include <stdint.h>

// ---------------------------------------------------------------------------
// Problem constants
#define B_ROWS   4096
#define T_LEN    3600
#define K_REAL   900        // folded length (period 1800, +/- fold at 900)
#define KP       928        // padded K (29 chunks of 32)
#define NCHUNK   29
#define DELTA    5

// Balanced n-tile layout: 4 q-tiles, cols interleaved (2u = cos, 2u+1 = sin):
//   q=0: even g base 40  (51 pairs, g=40..140)
//   q=1: even g base 142 (50 pairs, g=142..240)
//   q=2: odd  g base 41  (50 pairs, g=41..139)
//   q=3: odd  g base 141 (50 pairs, g=141..239)
// Real cols <= 102 per tile; cols 112..127 never touched by MMA.
// parity p = q >> 1

// ---------------------------------------------------------------------------
// Static device scratch (fp16 operands)
__device__ __half g_Y[2][(size_t)B_ROWS * KP];   // A, 15.2 MB
__device__ __half g_B[4][(size_t)128 * KP];      // B, ~0.95 MB
__device__ float  g_w8[8][B_ROWS];    // [q*2 + ngroup][row], pure writes
__device__ float  g_u8[8][B_ROWS];
__device__ double g_part[16];
__device__ unsigned int g_done = 0;   // self-resetting arrival counter

__device__ __constant__ int c_gbase[4]  = {40, 142, 41, 141};
__device__ __constant__ int c_npairs[4] = {51, 50, 50, 50};

// ---------------------------------------------------------------------------
__device__ __forceinline__ uint32_t smem_u32(const void* p) {
    uint32_t a;
    asm("{ .reg .u64 t; cvta.to.shared.u64 t, %1; cvt.u32.u64 %0, t; }"
        : "=r"(a) : "l"(p));
    return a;
}
__device__ __forceinline__ void ldsm4(uint32_t& r0, uint32_t& r1,
                                      uint32_t& r2, uint32_t& r3, uint32_t addr) {
    asm volatile("ldmatrix.sync.aligned.m8n8.x4.shared.b16 {%0,%1,%2,%3}, [%4];"
                 : "=r"(r0), "=r"(r1), "=r"(r2), "=r"(r3) : "r"(addr));
}
__device__ __forceinline__ void mma16816(float* d, const uint32_t* a,
                                         uint32_t b0, uint32_t b1) {
    asm volatile(
        "mma.sync.aligned.m16n8k16.row.col.f32.f16.f16.f32 "
        "{%0,%1,%2,%3}, {%4,%5,%6,%7}, {%8,%9}, {%0,%1,%2,%3};"
        : "+f"(d[0]), "+f"(d[1]), "+f"(d[2]), "+f"(d[3])
        : "r"(a[0]), "r"(a[1]), "r"(a[2]), "r"(a[3]), "r"(b0), "r"(b1));
}

// ---------------------------------------------------------------------------
// Prep: basis (blocks [0,1856)) + fold (blocks [1856,5568))
#define NB_BASIS 1856                 // 4*128*928/256
#define NB_FOLD  3712                 // 4096*(928/4)/256

__global__ void prep_kernel(const float* __restrict__ x) {
    if (blockIdx.x < NB_BASIS) {
        int idx = blockIdx.x * 256 + threadIdx.x;
        int q   = idx / (128 * KP);
        int rem = idx - q * 128 * KP;
        int r   = rem / KP;
        int t   = rem - r * KP;
        int u    = r >> 1;
        int comp = r & 1;
        float v = 0.0f;
        if (u < c_npairs[q] && t < K_REAL) {
            int g  = c_gbase[q] + 2 * u;
            int ri = (g * t) % 1800;
            float ang = (float)((double)ri * (6.283185307179586476925287 / 1800.0));
            v = comp ? sinf(ang) : cosf(ang);
        }
        ((__half*)g_B)[idx] = __float2half_rn(v);
    } else {
        int idx = (blockIdx.x - NB_BASIS) * 256 + threadIdx.x;
        int b  = idx / (KP / 4);          // 232 threads per row
        int tc = idx - b * (KP / 4);
        int t0 = tc * 4;
        float ye[4], yo[4];
        const float* xr = x + (size_t)b * T_LEN;
        if (t0 + 3 < K_REAL) {
            float4 x0 = *(const float4*)(xr + t0);
            float4 x1 = *(const float4*)(xr + t0 + 900);
            float4 x2 = *(const float4*)(xr + t0 + 1800);
            float4 x3 = *(const float4*)(xr + t0 + 2700);
            float s02, s13;
            s02 = x0.x + x2.x; s13 = x1.x + x3.x; ye[0] = s02 + s13; yo[0] = s02 - s13;
            s02 = x0.y + x2.y; s13 = x1.y + x3.y; ye[1] = s02 + s13; yo[1] = s02 - s13;
            s02 = x0.z + x2.z; s13 = x1.z + x3.z; ye[2] = s02 + s13; yo[2] = s02 - s13;
            s02 = x0.w + x2.w; s13 = x1.w + x3.w; ye[3] = s02 + s13; yo[3] = s02 - s13;
        } else {
            #pragma unroll
            for (int i = 0; i < 4; i++) {
                int t = t0 + i;
                float e = 0.0f, o = 0.0f;
                if (t < K_REAL) {
                    float s02 = xr[t] + xr[t + 1800];
                    float s13 = xr[t + 900] + xr[t + 2700];
                    e = s02 + s13; o = s02 - s13;
                }
                ye[i] = e; yo[i] = o;
            }
        }
        union { __half h[4]; uint2 v; } eh, oh;
        #pragma unroll
        for (int i = 0; i < 4; i++) {
            eh.h[i] = __float2half_rn(ye[i]);
            oh.h[i] = __float2half_rn(yo[i]);
        }
        size_t o = (size_t)b * KP + t0;
        *(uint2*)(&g_Y[0][o]) = eh.v;
        *(uint2*)(&g_Y[1][o]) = oh.v;
    }
}

// ---------------------------------------------------------------------------
// mma.sync fp16 GEMM + fused PSD/band epilogue (single term).
// CTA 128x128(112 real), BK=32, 256 threads.
// Warp map: mw=(wid&3)*32, nw=(wid>>2)*64 -> each SMSP gets one full
// (4-ng) and one reduced (3-ng) warp: 7 ng per SMSP instead of 8.
#define ASTRIDE 40                   // fp16 per SMEM row (80B)
#define TB      (128 * ASTRIDE * 2)  // tile bytes = 10240

__global__ void __launch_bounds__(256) gemm_mma_kernel(const int* __restrict__ f_true) {
    extern __shared__ char smem[];   // [2 stages][2 tiles][TB]
    const uint32_t smb = smem_u32(smem);

    int tid  = threadIdx.x;
    int wid  = tid >> 5;
    int lane = tid & 31;
    int q  = blockIdx.y;
    int p  = q >> 1;
    int m0 = blockIdx.x * 128;

    const __half* __restrict__ Ap = g_Y[p] + (size_t)m0 * KP;
    const __half* __restrict__ Bp = g_B[q];

    // load mapping: row = tid>>1, 32B half = tid&1
    int grow = tid >> 1;
    int ghal = tid & 1;
    size_t   gofs = (size_t)grow * KP + ghal * 16;
    uint32_t sofs = (uint32_t)(grow * 80 + ghal * 32);

    // warp tile (SMSP-balanced): SMSP s hosts wid s (nw=0) + wid s+4 (nw=64)
    int mw = (wid & 3) * 32;    // 0,32,64,96
    int nw = (wid >> 2) * 64;   // 0,64
    int full = (nw == 0);       // full warps do 4 ng; reduced do 3

    uint32_t offA = (uint32_t)((mw + (lane & 15)) * ASTRIDE + (lane >> 4) * 8) * 2;
    int bsel = lane >> 3;
    uint32_t offB = (uint32_t)((nw + (bsel >> 1) * 8 + (lane & 7)) * ASTRIDE
                               + (bsel & 1) * 8) * 2;

    float acc[2][8][4];
    #pragma unroll
    for (int i = 0; i < 2; i++)
        #pragma unroll
        for (int j = 0; j < 8; j++)
            #pragma unroll
            for (int c = 0; c < 4; c++) acc[i][j][c] = 0.0f;

    // preload stage 0
    {
        uint4 v;
        v = *(const uint4*)(Ap + gofs);      *(uint4*)(smem + 0*TB + sofs) = v;
        v = *(const uint4*)(Ap + gofs + 8);  *(uint4*)(smem + 0*TB + sofs + 16) = v;
        v = *(const uint4*)(Bp + gofs);      *(uint4*)(smem + 1*TB + sofs) = v;
        v = *(const uint4*)(Bp + gofs + 8);  *(uint4*)(smem + 1*TB + sofs + 16) = v;
    }
    __syncthreads();

    for (int k = 0; k < NCHUNK; k++) {
        int cur = k & 1;
        uint4 nx[4];
        if (k + 1 < NCHUNK) {
            size_t gk = gofs + (k + 1) * 32;
            nx[0] = *(const uint4*)(Ap + gk);  nx[1] = *(const uint4*)(Ap + gk + 8);
            nx[2] = *(const uint4*)(Bp + gk);  nx[3] = *(const uint4*)(Bp + gk + 8);
        }

        uint32_t sbase = smb + cur * 2 * TB;
        #pragma unroll
        for (int kk = 0; kk < 32; kk += 16) {
            uint32_t ar[2][4];
            #pragma unroll
            for (int mf = 0; mf < 2; mf++) {
                uint32_t ao = offA + (uint32_t)(mf * 16 * ASTRIDE * 2) + kk * 2;
                ldsm4(ar[mf][0], ar[mf][1], ar[mf][2], ar[mf][3], sbase + 0*TB + ao);
            }
            #pragma unroll
            for (int ng = 0; ng < 4; ng++) {
                if (ng == 3 && !full) break;   // reduced warps: cols 112..127 unused
                uint32_t bo = offB + (uint32_t)(ng * 16 * ASTRIDE * 2) + kk * 2;
                uint32_t b0, b1, b2, b3;
                ldsm4(b0, b1, b2, b3, sbase + 1*TB + bo);
                #pragma unroll
                for (int mf = 0; mf < 2; mf++) {
                    mma16816(acc[mf][ng*2],   ar[mf], b0, b1);
                    mma16816(acc[mf][ng*2+1], ar[mf], b2, b3);
                }
            }
        }
        // Store to the opposite buffer; its last readers (iter k-1) are
        // already ordered via the previous end-of-chunk barrier.
        if (k + 1 < NCHUNK) {
            char* st = smem + ((k + 1) & 1) * 2 * TB;
            *(uint4*)(st + 0*TB + sofs)      = nx[0];
            *(uint4*)(st + 0*TB + sofs + 16) = nx[1];
            *(uint4*)(st + 1*TB + sofs)      = nx[2];
            *(uint4*)(st + 1*TB + sofs + 16) = nx[3];
            __syncthreads();
        }
    }

    // Fused epilogue: PSD + band sums; pure writes to per-(q, ngroup) slices.
    // Reduced warps' nf=6,7 accumulators stay 0 (init) -> contribute nothing.
    int gbase = c_gbase[q];
    int slice = q * 2 + (nw >> 6);
    #pragma unroll
    for (int mf = 0; mf < 2; mf++) {
        #pragma unroll
        for (int half = 0; half < 2; half++) {
            int row = m0 + mw + mf * 16 + (lane >> 2) + half * 8;
            int f = __ldg(&f_true[row]);
            float w = 0.0f, u = 0.0f;
            #pragma unroll
            for (int nf = 0; nf < 8; nf++) {
                float c = acc[mf][nf][half * 2];
                float s = acc[mf][nf][half * 2 + 1];
                float psd = c * c + s * s;
                int g = gbase + 2 * ((nw >> 1) + nf * 4 + (lane & 3));
                int d = g - f; if (d < 0) d = -d;
                if (d <= DELTA) w += psd; else u += psd;
            }
            w += __shfl_xor_sync(0xFFFFFFFFu, w, 1);
            w += __shfl_xor_sync(0xFFFFFFFFu, w, 2);
            u += __shfl_xor_sync(0xFFFFFFFFu, u, 1);
            u += __shfl_xor_sync(0xFFFFFFFFu, u, 2);
            if ((lane & 3) == 0) {
                g_w8[slice][row] = w;
                g_u8[slice][row] = u;
            }
        }
    }
}

// Per-row SNR -> mean -> out. 16 blocks; last-arriving block finalizes.
__global__ void reduce_kernel(float* __restrict__ out) {
    int tid = threadIdx.x;
    int r = blockIdx.x * 256 + tid;
    float w = 0.0f, u = 0.0f;
    #pragma unroll
    for (int i = 0; i < 8; i++) { w += g_w8[i][r]; u += g_u8[i][r]; }
    float snr = 10.0f * log10f((w * 190.0f) / (u * 11.0f));
    __shared__ double sh[256];
    sh[tid] = (double)snr;
    __syncthreads();
    for (int off = 128; off > 0; off >>= 1) {
        if (tid < off) sh[tid] += sh[tid + off];
        __syncthreads();
    }
    if (tid == 0) {
        g_part[blockIdx.x] = sh[0];
        __threadfence();
        if (atomicAdd(&g_done, 1u) == 15u) {
            double s = 0.0;
            #pragma unroll
            for (int i = 0; i < 16; i++) s += g_part[i];
            out[0] = (float)(-s * (1.0 / 4096.0));
            g_done = 0;   // reset for graph replay
        }
    }
}

// ---------------------------------------------------------------------------
extern "C" void kernel_launch(void* const* d_in, const int* in_sizes, int n_in,
                              void* d_out, int out_size) {
    const float* x      = (const float*)d_in[0];
    const int*   f_true = (const int*)d_in[1];
    float*       out    = (float*)d_out;

    const int GEMM_SMEM = 2 * 2 * TB;   // 40960 bytes
    cudaFuncSetAttribute(gemm_mma_kernel,
                         cudaFuncAttributeMaxDynamicSharedMemorySize, GEMM_SMEM);

    prep_kernel<<<NB_BASIS + NB_FOLD, 256>>>(x);
    gemm_mma_kernel<<<dim3(B_ROWS / 128, 4), 256, GEMM_SMEM>>>(f_true);
    reduce_kernel<<<16, 256>>>(out);
}

// round 17
// speedup vs baseline: 1.0657x; 1.0657x over previous
#include <cuda_runtime.h>
#include <cuda_fp16.h>
#include <math.h>
#include <stdint.h>

// ---------------------------------------------------------------------------
// Problem constants
#define B_ROWS   4096
#define T_LEN    3600
#define K_REAL   900        // folded length (period 1800, +/- fold at 900)
#define KP       928        // padded K (29 chunks of 32)
#define NCHUNK   29
#define DELTA    5

// Balanced n-tile layout: 4 q-tiles, cols interleaved (2u = cos, 2u+1 = sin):
//   q=0: even g base 40  (51 pairs), q=1: even base 142 (50 pairs)
//   q=2: odd  g base 41  (50 pairs), q=3: odd  base 141 (50 pairs)
// Real cols <= 102 per tile; cols 112..127 never touched by MMA.
// parity p = q >> 1

// ---------------------------------------------------------------------------
// Static device scratch (fp16 operands)
__device__ __half g_Y[2][(size_t)B_ROWS * KP];   // A, 15.2 MB
__device__ __half g_B[4][(size_t)128 * KP];      // B, ~0.95 MB
__device__ float  g_w8[8][B_ROWS];    // [q*2 + ngroup][row], pure writes
__device__ float  g_u8[8][B_ROWS];
__device__ double g_part[16];
__device__ unsigned int g_done = 0;   // self-resetting arrival counter

__device__ __constant__ int c_gbase[4]  = {40, 142, 41, 141};
__device__ __constant__ int c_npairs[4] = {51, 50, 50, 50};

// ---------------------------------------------------------------------------
__device__ __forceinline__ uint32_t smem_u32(const void* p) {
    uint32_t a;
    asm("{ .reg .u64 t; cvta.to.shared.u64 t, %1; cvt.u32.u64 %0, t; }"
        : "=r"(a) : "l"(p));
    return a;
}
__device__ __forceinline__ void ldsm4(uint32_t& r0, uint32_t& r1,
                                      uint32_t& r2, uint32_t& r3, uint32_t addr) {
    asm volatile("ldmatrix.sync.aligned.m8n8.x4.shared.b16 {%0,%1,%2,%3}, [%4];"
                 : "=r"(r0), "=r"(r1), "=r"(r2), "=r"(r3) : "r"(addr));
}
__device__ __forceinline__ void mma16816(float* d, const uint32_t* a,
                                         uint32_t b0, uint32_t b1) {
    asm volatile(
        "mma.sync.aligned.m16n8k16.row.col.f32.f16.f16.f32 "
        "{%0,%1,%2,%3}, {%4,%5,%6,%7}, {%8,%9}, {%0,%1,%2,%3};"
        : "+f"(d[0]), "+f"(d[1]), "+f"(d[2]), "+f"(d[3])
        : "r"(a[0]), "r"(a[1]), "r"(a[2]), "r"(a[3]), "r"(b0), "r"(b1));
}

// ---------------------------------------------------------------------------
// Prep: fold first (blocks [0,3712)) -> DRAM streaming starts immediately;
// compact basis (blocks [3712,4176), 4 t per thread) fills the tail.
#define NB_FOLD  3712                 // 4096*(928/4)/256
#define NB_BASIS 464                  // 4*128*(928/4)/256

__global__ void prep_kernel(const float* __restrict__ x) {
    if (blockIdx.x < NB_FOLD) {
        int idx = blockIdx.x * 256 + threadIdx.x;
        int b  = idx / (KP / 4);          // 232 threads per row
        int tc = idx - b * (KP / 4);
        int t0 = tc * 4;
        float ye[4], yo[4];
        const float* xr = x + (size_t)b * T_LEN;
        if (t0 + 3 < K_REAL) {
            float4 x0 = *(const float4*)(xr + t0);
            float4 x1 = *(const float4*)(xr + t0 + 900);
            float4 x2 = *(const float4*)(xr + t0 + 1800);
            float4 x3 = *(const float4*)(xr + t0 + 2700);
            float s02, s13;
            s02 = x0.x + x2.x; s13 = x1.x + x3.x; ye[0] = s02 + s13; yo[0] = s02 - s13;
            s02 = x0.y + x2.y; s13 = x1.y + x3.y; ye[1] = s02 + s13; yo[1] = s02 - s13;
            s02 = x0.z + x2.z; s13 = x1.z + x3.z; ye[2] = s02 + s13; yo[2] = s02 - s13;
            s02 = x0.w + x2.w; s13 = x1.w + x3.w; ye[3] = s02 + s13; yo[3] = s02 - s13;
        } else {
            #pragma unroll
            for (int i = 0; i < 4; i++) {
                int t = t0 + i;
                float e = 0.0f, o = 0.0f;
                if (t < K_REAL) {
                    float s02 = xr[t] + xr[t + 1800];
                    float s13 = xr[t + 900] + xr[t + 2700];
                    e = s02 + s13; o = s02 - s13;
                }
                ye[i] = e; yo[i] = o;
            }
        }
        union { __half h[4]; uint2 v; } eh, oh;
        #pragma unroll
        for (int i = 0; i < 4; i++) {
            eh.h[i] = __float2half_rn(ye[i]);
            oh.h[i] = __float2half_rn(yo[i]);
        }
        size_t o = (size_t)b * KP + t0;
        *(uint2*)(&g_Y[0][o]) = eh.v;
        *(uint2*)(&g_Y[1][o]) = oh.v;
    } else {
        int idx = (blockIdx.x - NB_FOLD) * 256 + threadIdx.x;   // 4 elems each
        int q    = idx / (128 * (KP / 4));
        int rem  = idx - q * 128 * (KP / 4);
        int r    = rem / (KP / 4);
        int t0   = (rem - r * (KP / 4)) * 4;
        int u    = r >> 1;
        int comp = r & 1;
        int ok   = (u < c_npairs[q]);
        int g    = c_gbase[q] + 2 * u;
        union { __half h[4]; uint2 v; } hv;
        #pragma unroll
        for (int i = 0; i < 4; i++) {
            int t = t0 + i;
            float vv = 0.0f;
            if (ok && t < K_REAL) {
                int ri = (g * t) % 1800;
                float ang = (float)((double)ri * (6.283185307179586476925287 / 1800.0));
                vv = comp ? sinf(ang) : cosf(ang);
            }
            hv.h[i] = __float2half_rn(vv);
        }
        *(uint2*)(&g_B[q][(size_t)r * KP + t0]) = hv.v;
    }
}

// ---------------------------------------------------------------------------
// mma.sync fp16 GEMM + fused PSD/band epilogue (single term).
// CTA 128x128(112 real), BK=32, 256 threads, prefetch distance 2:
//   iter k: LDG chunk k+2 -> nx[k&1]; compute smem[k&1];
//           STS chunk k+1 from nx[(k+1)&1]; sync.
#define ASTRIDE 40                   // fp16 per SMEM row (80B)
#define TB      (128 * ASTRIDE * 2)  // tile bytes = 10240

__global__ void __launch_bounds__(256) gemm_mma_kernel(const int* __restrict__ f_true) {
    extern __shared__ char smem[];   // [2 stages][2 tiles][TB]
    const uint32_t smb = smem_u32(smem);

    int tid  = threadIdx.x;
    int wid  = tid >> 5;
    int lane = tid & 31;
    int q  = blockIdx.y;
    int p  = q >> 1;
    int m0 = blockIdx.x * 128;

    const __half* __restrict__ Ap = g_Y[p] + (size_t)m0 * KP;
    const __half* __restrict__ Bp = g_B[q];

    // load mapping: row = tid>>1, 32B half = tid&1
    int grow = tid >> 1;
    int ghal = tid & 1;
    size_t   gofs = (size_t)grow * KP + ghal * 16;
    uint32_t sofs = (uint32_t)(grow * 80 + ghal * 32);

    // warp tile (SMSP-balanced): SMSP s hosts wid s (nw=0) + wid s+4 (nw=64)
    int mw = (wid & 3) * 32;
    int nw = (wid >> 2) * 64;
    int full = (nw == 0);

    uint32_t offA = (uint32_t)((mw + (lane & 15)) * ASTRIDE + (lane >> 4) * 8) * 2;
    int bsel = lane >> 3;
    uint32_t offB = (uint32_t)((nw + (bsel >> 1) * 8 + (lane & 7)) * ASTRIDE
                               + (bsel & 1) * 8) * 2;

    float acc[2][8][4];
    #pragma unroll
    for (int i = 0; i < 2; i++)
        #pragma unroll
        for (int j = 0; j < 8; j++)
            #pragma unroll
            for (int c = 0; c < 4; c++) acc[i][j][c] = 0.0f;

    uint4 nx[2][4];

    // prologue: chunk0 direct to smem stage 0; chunk1 -> nx[1]
    {
        uint4 v;
        v = *(const uint4*)(Ap + gofs);      *(uint4*)(smem + 0*TB + sofs) = v;
        v = *(const uint4*)(Ap + gofs + 8);  *(uint4*)(smem + 0*TB + sofs + 16) = v;
        v = *(const uint4*)(Bp + gofs);      *(uint4*)(smem + 1*TB + sofs) = v;
        v = *(const uint4*)(Bp + gofs + 8);  *(uint4*)(smem + 1*TB + sofs + 16) = v;
        size_t g1 = gofs + 32;
        nx[1][0] = *(const uint4*)(Ap + g1);  nx[1][1] = *(const uint4*)(Ap + g1 + 8);
        nx[1][2] = *(const uint4*)(Bp + g1);  nx[1][3] = *(const uint4*)(Bp + g1 + 8);
    }
    __syncthreads();

    #pragma unroll 2
    for (int k = 0; k < NCHUNK; k++) {
        int par = k & 1;
        if (k + 2 < NCHUNK) {
            size_t gk = gofs + (size_t)(k + 2) * 32;
            nx[par][0] = *(const uint4*)(Ap + gk);  nx[par][1] = *(const uint4*)(Ap + gk + 8);
            nx[par][2] = *(const uint4*)(Bp + gk);  nx[par][3] = *(const uint4*)(Bp + gk + 8);
        }

        uint32_t sbase = smb + par * 2 * TB;
        #pragma unroll
        for (int kk = 0; kk < 32; kk += 16) {
            uint32_t ar[2][4];
            #pragma unroll
            for (int mf = 0; mf < 2; mf++) {
                uint32_t ao = offA + (uint32_t)(mf * 16 * ASTRIDE * 2) + kk * 2;
                ldsm4(ar[mf][0], ar[mf][1], ar[mf][2], ar[mf][3], sbase + 0*TB + ao);
            }
            #pragma unroll
            for (int ng = 0; ng < 4; ng++) {
                if (ng == 3 && !full) break;   // reduced warps: cols 112..127 unused
                uint32_t bo = offB + (uint32_t)(ng * 16 * ASTRIDE * 2) + kk * 2;
                uint32_t b0, b1, b2, b3;
                ldsm4(b0, b1, b2, b3, sbase + 1*TB + bo);
                #pragma unroll
                for (int mf = 0; mf < 2; mf++) {
                    mma16816(acc[mf][ng*2],   ar[mf], b0, b1);
                    mma16816(acc[mf][ng*2+1], ar[mf], b2, b3);
                }
            }
        }
        // STS chunk k+1 (loaded during iter k-1) to the opposite buffer,
        // whose last readers passed the previous end-of-chunk barrier.
        if (k + 1 < NCHUNK) {
            char* st = smem + (1 - par) * 2 * TB;
            int np = 1 - par;
            *(uint4*)(st + 0*TB + sofs)      = nx[np][0];
            *(uint4*)(st + 0*TB + sofs + 16) = nx[np][1];
            *(uint4*)(st + 1*TB + sofs)      = nx[np][2];
            *(uint4*)(st + 1*TB + sofs + 16) = nx[np][3];
            __syncthreads();
        }
    }

    // Fused epilogue: PSD + band sums; pure writes to per-(q, ngroup) slices.
    // Reduced warps' nf=6,7 accumulators stay 0 (init) -> contribute nothing.
    int gbase = c_gbase[q];
    int slice = q * 2 + (nw >> 6);
    #pragma unroll
    for (int mf = 0; mf < 2; mf++) {
        #pragma unroll
        for (int half = 0; half < 2; half++) {
            int row = m0 + mw + mf * 16 + (lane >> 2) + half * 8;
            int f = __ldg(&f_true[row]);
            float w = 0.0f, u = 0.0f;
            #pragma unroll
            for (int nf = 0; nf < 8; nf++) {
                float c = acc[mf][nf][half * 2];
                float s = acc[mf][nf][half * 2 + 1];
                float psd = c * c + s * s;
                int g = gbase + 2 * ((nw >> 1) + nf * 4 + (lane & 3));
                int d = g - f; if (d < 0) d = -d;
                if (d <= DELTA) w += psd; else u += psd;
            }
            w += __shfl_xor_sync(0xFFFFFFFFu, w, 1);
            w += __shfl_xor_sync(0xFFFFFFFFu, w, 2);
            u += __shfl_xor_sync(0xFFFFFFFFu, u, 1);
            u += __shfl_xor_sync(0xFFFFFFFFu, u, 2);
            if ((lane & 3) == 0) {
                g_w8[slice][row] = w;
                g_u8[slice][row] = u;
            }
        }
    }
}

// Per-row SNR -> mean -> out. 16 blocks; last-arriving block finalizes.
__global__ void reduce_kernel(float* __restrict__ out) {
    int tid = threadIdx.x;
    int r = blockIdx.x * 256 + tid;
    float w = 0.0f, u = 0.0f;
    #pragma unroll
    for (int i = 0; i < 8; i++) { w += g_w8[i][r]; u += g_u8[i][r]; }
    float snr = 10.0f * log10f((w * 190.0f) / (u * 11.0f));
    __shared__ double sh[256];
    sh[tid] = (double)snr;
    __syncthreads();
    for (int off = 128; off > 0; off >>= 1) {
        if (tid < off) sh[tid] += sh[tid + off];
        __syncthreads();
    }
    if (tid == 0) {
        g_part[blockIdx.x] = sh[0];
        __threadfence();
        if (atomicAdd(&g_done, 1u) == 15u) {
            double s = 0.0;
            #pragma unroll
            for (int i = 0; i < 16; i++) s += g_part[i];
            out[0] = (float)(-s * (1.0 / 4096.0));
            g_done = 0;   // reset for graph replay
        }
    }
}

// ---------------------------------------------------------------------------
extern "C" void kernel_launch(void* const* d_in, const int* in_sizes, int n_in,
                              void* d_out, int out_size) {
    const float* x      = (const float*)d_in[0];
    const int*   f_true = (const int*)d_in[1];
    float*       out    = (float*)d_out;

    const int GEMM_SMEM = 2 * 2 * TB;   // 40960 bytes
    cudaFuncSetAttribute(gemm_mma_kernel,
                         cudaFuncAttributeMaxDynamicSharedMemorySize, GEMM_SMEM);

    prep_kernel<<<NB_FOLD + NB_BASIS, 256>>>(x);
    gemm_mma_kernel<<<dim3(B_ROWS / 128, 4), 256, GEMM_SMEM>>>(f_true);
    reduce_kernel<<<16, 256>>>(out);
}